// round 16
// baseline (speedup 1.0000x reference)
#include <cuda_runtime.h>
#include <cuda_fp16.h>
#include <cstdint>
#include <cstddef>

// Problem constants
#define BATCH 4
#define NPTS  16384
#define SPTS  4096
#define CF    128
#define CC    256
#define CIN   384
#define CMID  192
#define COUT  128
#define GROUPS 8
#define EPS_GN 1e-5f
#define EPS_D  1e-8f
#define BN_TOTAL (BATCH * NPTS)   // 65536
#define CTAS_PER_BATCH 128

// -------------------- scratch (device globals; no allocation) --------------------
__device__ __align__(16) __half g_h1[(size_t)BN_TOTAL * CMID];        // 25 MB
__device__ __align__(16) __half g_P[(size_t)BATCH * SPTS * CMID];     // 6.3 MB
__device__ int   g_idx[(size_t)BN_TOTAL * 3];
__device__ float g_wt[(size_t)BN_TOTAL * 3];
__device__ __align__(16) __half g_w1h[CMID * CIN];
__device__ __align__(16) __half g_w2h[COUT * CMID];
__device__ float g_part1[2 * 32 * CTAS_PER_BATCH];
__device__ float g_part2[2 * 32 * CTAS_PER_BATCH];
__device__ float g_a1[BATCH * CMID], g_b1[BATCH * CMID];
__device__ float g_a2[BATCH * COUT], g_b2[BATCH * COUT];

// ==================== helpers ====================
__device__ __forceinline__ uint32_t smem_u32(const void* p) {
    uint32_t a;
    asm("{ .reg .u64 t; cvta.to.shared.u64 t, %1; cvt.u32.u64 %0, t; }" : "=r"(a) : "l"(p));
    return a;
}
#define LDSM4(r0, r1, r2, r3, addr) \
    asm volatile("ldmatrix.sync.aligned.m8n8.x4.shared.b16 {%0,%1,%2,%3}, [%4];" \
        : "=r"(r0), "=r"(r1), "=r"(r2), "=r"(r3) : "r"(addr))
#define MMA16816(d, a0, a1, a2, a3, b0, b1) \
    asm volatile("mma.sync.aligned.m16n8k16.row.col.f32.f16.f16.f32 " \
        "{%0,%1,%2,%3},{%4,%5,%6,%7},{%8,%9},{%0,%1,%2,%3};" \
        : "+f"((d)[0]), "+f"((d)[1]), "+f"((d)[2]), "+f"((d)[3]) \
        : "r"(a0), "r"(a1), "r"(a2), "r"(a3), "r"(b0), "r"(b1))
#define CP16(dst, src) \
    asm volatile("cp.async.cg.shared.global [%0], [%1], 16;" :: "r"(dst), "l"(src))
#define CP_COMMIT() asm volatile("cp.async.commit_group;" ::: "memory")
#define CP_WAIT1()  asm volatile("cp.async.wait_group 1;" ::: "memory")
#define CP_WAIT0()  asm volatile("cp.async.wait_group 0;" ::: "memory")

__device__ __forceinline__ uint32_t pack2(float x, float y) {
    __half hx = __float2half_rn(x), hy = __float2half_rn(y);
    return ((uint32_t)__half_as_ushort(hy) << 16) | __half_as_ushort(hx);
}

// ==================== Kernel 1: kNN (K=3) + IDW weights ====================
#define KNN_CHUNK 2048
__global__ void __launch_bounds__(128) knn_kernel(
    const float* __restrict__ fxyz, const float* __restrict__ cxyz,
    int* __restrict__ oidx, float* __restrict__ owt)
{
    __shared__ float4 cs[KNN_CHUNK];
    const int b = blockIdx.y;
    const int n = blockIdx.x * 128 + threadIdx.x;
    const float* fp = fxyz + ((size_t)b * NPTS + n) * 3;
    const float qx = fp[0], qy = fp[1], qz = fp[2];

    float s0 = 3.4e38f, s1 = 3.4e38f, s2 = 3.4e38f;
    int   i0 = 0, i1 = 0, i2 = 0;

    auto insert = [&](float sc, int iv) {
        if (sc < s1) {
            s2 = s1; i2 = i1;
            if (sc < s0) { s1 = s0; i1 = i0; s0 = sc; i0 = iv; }
            else         { s1 = sc; i1 = iv; }
        } else { s2 = sc; i2 = iv; }
    };

    for (int c0 = 0; c0 < SPTS; c0 += KNN_CHUNK) {
        __syncthreads();
        for (int j = threadIdx.x; j < KNN_CHUNK; j += 128) {
            const float* cp = cxyz + ((size_t)b * SPTS + c0 + j) * 3;
            float x = cp[0], y = cp[1], z = cp[2];
            cs[j] = make_float4(-2.0f * x, -2.0f * y, -2.0f * z, x*x + y*y + z*z);
        }
        __syncthreads();
        // score = ||c||^2 - 2 q.c (reference score minus per-thread const ||q||^2)
        #pragma unroll 4
        for (int j = 0; j < KNN_CHUNK; j += 2) {
            float4 ca = cs[j], cb = cs[j + 1];
            float sa  = fmaf(qx, ca.x, fmaf(qy, ca.y, fmaf(qz, ca.z, ca.w)));
            float sb2 = fmaf(qx, cb.x, fmaf(qy, cb.y, fmaf(qz, cb.z, cb.w)));
            if (fminf(sa, sb2) < s2) {
                if (sa  < s2) insert(sa,  c0 + j);
                if (sb2 < s2) insert(sb2, c0 + j + 1);
            }
        }
    }
    int ii[3] = { i0, i1, i2 };
    float w[3], wsum = 0.0f;
    #pragma unroll
    for (int k = 0; k < 3; k++) {
        const float* cp = cxyz + ((size_t)b * SPTS + ii[k]) * 3;
        float dx = qx - cp[0], dy = qy - cp[1], dz = qz - cp[2];
        float d2 = fmaxf(dx*dx + dy*dy + dz*dz, EPS_D);
        w[k] = 1.0f / d2; wsum += w[k];
    }
    float inv = 1.0f / wsum;
    size_t base = ((size_t)b * NPTS + n) * 3;
    #pragma unroll
    for (int k = 0; k < 3; k++) { oidx[base + k] = ii[k]; owt[base + k] = w[k] * inv; }
}

// ==================== Kernel 2: weights -> fp16 ====================
__global__ void prep_weights(const float* __restrict__ w1, const float* __restrict__ w2,
                             __half* w1h, __half* w2h)
{
    int i = blockIdx.x * 256 + threadIdx.x;
    if (i < CMID * CIN) w1h[i] = __float2half_rn(w1[i]);
    int j = i - CMID * CIN;
    if (j >= 0 && j < COUT * CMID) w2h[j] = __float2half_rn(w2[j]);
}

// ==================== P-GEMM: P[b,s,:] = cfeat[b,s,:] @ W1coarse^T ====================
#define P_A32 0
#define P_B   20480
#define P_STAGE 35840
#define P_CONV (3 * P_STAGE)            // 107520
#define P_SMEM (P_CONV + 10240)         // 117760

__global__ void __launch_bounds__(512) pgemm_mma(
    const float* __restrict__ cfeat, const __half* __restrict__ Bw,
    __half* __restrict__ P)
{
    extern __shared__ char smem[];
    const uint32_t sb = smem_u32(smem);
    const int tid = threadIdx.x, lane = tid & 31, wid = tid >> 5;
    const int wm = wid & 3, wn = wid >> 2;
    const int bb = blockIdx.x >> 5;
    const int m0 = (blockIdx.x & 31) * 128;

    auto issue = [&](int it, int buf) {
        const int kc0 = it * 32;
        const uint32_t base = sb + buf * P_STAGE;
        #pragma unroll
        for (int u = 0; u < 2; u++) {
            int i = u * 512 + tid;
            int row = i >> 3, ko = (i & 7) * 4;
            CP16(base + P_A32 + row * 160 + ko * 4,
                 cfeat + ((size_t)bb * SPTS + m0 + row) * CC + kc0 + ko);
        }
        #pragma unroll
        for (int q = 0; q < 2; q++) {
            int i = q * 512 + tid;
            if (i < 768) {
                int row = i >> 2, ko = (i & 3) * 8;
                CP16(base + P_B + row * 80 + ko * 2, Bw + (size_t)row * CIN + 128 + kc0 + ko);
            }
        }
    };

    float acc[2][6][4];
    #pragma unroll
    for (int i = 0; i < 2; i++)
        #pragma unroll
        for (int j = 0; j < 6; j++)
            #pragma unroll
            for (int k = 0; k < 4; k++) acc[i][j][k] = 0.0f;

    issue(0, 0); CP_COMMIT();
    issue(1, 1); CP_COMMIT();

    const int crow = tid >> 2, cko = (tid & 3) * 8;
    const int lrow = lane & 15, lk = (lane >> 4) * 8;
    for (int it = 0; it < 8; it++) {
        CP_WAIT1();
        __syncthreads();
        if (it + 2 < 8) issue(it + 2, (it + 2) % 3);   // 3-stage: safe before compute
        CP_COMMIT();
        const uint32_t bufb = sb + (it % 3) * P_STAGE;
        {
            const float* rowp = (const float*)(smem + (it % 3) * P_STAGE + P_A32) + crow * 40 + cko;
            uint32_t hq[4];
            #pragma unroll
            for (int e = 0; e < 4; e++) hq[e] = pack2(rowp[e*2], rowp[e*2+1]);
            *(uint4*)(smem + P_CONV + crow * 80 + cko * 2) = make_uint4(hq[0], hq[1], hq[2], hq[3]);
        }
        __syncthreads();
        #pragma unroll
        for (int s = 0; s < 2; s++) {
            const int kc = s * 16;
            uint32_t fA[2][4];
            #pragma unroll
            for (int mf = 0; mf < 2; mf++) {
                uint32_t off = (uint32_t)(((wm * 32 + mf * 16 + lrow) * 40 + kc + lk) * 2);
                LDSM4(fA[mf][0], fA[mf][1], fA[mf][2], fA[mf][3], sb + P_CONV + off);
            }
            uint32_t fB[6][2];
            #pragma unroll
            for (int q = 0; q < 3; q++) {
                uint32_t off = (uint32_t)(((wn * 48 + q * 16 + lrow) * 40 + kc + lk) * 2);
                uint32_t r0, r1, r2, r3;
                LDSM4(r0, r1, r2, r3, bufb + P_B + off);
                fB[q*2][0] = r0; fB[q*2][1] = r2;
                fB[q*2+1][0] = r1; fB[q*2+1][1] = r3;
            }
            #pragma unroll
            for (int mf = 0; mf < 2; mf++)
                #pragma unroll
                for (int nf = 0; nf < 6; nf++)
                    MMA16816(acc[mf][nf], fA[mf][0], fA[mf][1], fA[mf][2], fA[mf][3],
                             fB[nf][0], fB[nf][1]);
        }
        __syncthreads();
    }

    const int g = lane >> 2, tig = lane & 3;
    #pragma unroll
    for (int mf = 0; mf < 2; mf++)
        #pragma unroll
        for (int nf = 0; nf < 6; nf++) {
            int row = m0 + wm * 32 + mf * 16 + g;
            int col = wn * 48 + nf * 8 + tig * 2;
            size_t base = ((size_t)bb * SPTS + row) * CMID + col;
            *(uint32_t*)(P + base)              = pack2(acc[mf][nf][0], acc[mf][nf][1]);
            *(uint32_t*)(P + base + 8 * CMID)   = pack2(acc[mf][nf][2], acc[mf][nf][3]);
        }
}

// ==================== GEMM1 (K=128 fine) + cp.async P-gather + GN1 stats ====================
// h1 = fine_feat @ W1fine^T + sum_k w_k * P[idx_k]
// Gathers are prefetched into smem via cp.async, interleaved with the mainloop.
#define F_A32 0
#define F_B   20480
#define F_STAGE 35840                   // A32 20480 + B 15360
#define F_CONV (2 * F_STAGE)            // 71680 (10240)
#define F_G    (F_CONV + 10240)         // 81920: 3 x (128 rows x 384 B) = 147456
#define F_IDX  (F_G + 147456)           // 229376 (1536)
#define F_WT   (F_IDX + 1536)           // 230912 (1536)
#define F_SMEM (F_WT + 1536)            // 232448 = 227 KB exactly

__global__ void __launch_bounds__(512) gemm1_mma(
    const float* __restrict__ ffeat, const __half* __restrict__ Pm,
    const int* __restrict__ idx, const float* __restrict__ wt,
    const __half* __restrict__ Bw,
    __half* __restrict__ C, float* __restrict__ part)
{
    extern __shared__ char smem[];
    const uint32_t sb = smem_u32(smem);
    const int tid = threadIdx.x, lane = tid & 31, wid = tid >> 5;
    const int wm = wid & 3, wn = wid >> 2;
    const int m0 = blockIdx.x * 128;
    const int bb = blockIdx.x >> 7;

    int*   s_idx = (int*)(smem + F_IDX);
    float* s_wt  = (float*)(smem + F_WT);
    if (tid < 384) {
        int row = tid / 3, k = tid - row * 3;
        s_idx[tid] = idx[((size_t)(m0 + row)) * 3 + k];
        s_wt[tid]  = wt[((size_t)(m0 + row)) * 3 + k];
    }

    auto issue = [&](int it, int buf) {
        const int kc0 = it * 32;
        const uint32_t base = sb + buf * F_STAGE;
        #pragma unroll
        for (int u = 0; u < 2; u++) {     // A32: 1024 CP16 (fine_feat)
            int i = u * 512 + tid;
            int row = i >> 3, ko = (i & 7) * 4;
            CP16(base + F_A32 + row * 160 + ko * 4,
                 ffeat + (size_t)(m0 + row) * CF + kc0 + ko);
        }
        #pragma unroll
        for (int q = 0; q < 2; q++) {     // B: 768 CP16 (w1h cols 0..127)
            int i = q * 512 + tid;
            if (i < 768) {
                int row = i >> 2, ko = (i & 3) * 8;
                CP16(base + F_B + row * 80 + ko * 2, Bw + (size_t)row * CIN + kc0 + ko);
            }
        }
    };
    // gather chunk c of 4: 2304 CP16 each (total 9216 = 3 nbrs x 128 rows x 24 chunks)
    auto gather = [&](int c) {
        #pragma unroll
        for (int u = 0; u < 5; u++) {
            int i = c * 2304 + u * 512 + tid;
            if (i < (c + 1) * 2304 && i < 9216) {
                int q  = i / 3072;
                int rm = i - q * 3072;
                int r  = rm / 24, ch = rm - r * 24;
                CP16(sb + F_G + q * 49152 + r * 384 + ch * 16,
                     Pm + ((size_t)bb * SPTS + s_idx[r * 3 + q]) * CMID + ch * 8);
            }
        }
    };

    float acc[2][6][4];
    #pragma unroll
    for (int i = 0; i < 2; i++)
        #pragma unroll
        for (int j = 0; j < 6; j++)
            #pragma unroll
            for (int k = 0; k < 4; k++) acc[i][j][k] = 0.0f;

    __syncthreads();     // s_idx/s_wt visible (needed by gather + epilogue)
    issue(0, 0); CP_COMMIT();
    issue(1, 1); CP_COMMIT();

    const int crow = tid >> 2, cko = (tid & 3) * 8;
    const int lrow = lane & 15, lk = (lane >> 4) * 8;
    for (int it = 0; it < 4; it++) {
        CP_WAIT1();
        __syncthreads();
        const uint32_t bufb = sb + (it & 1) * F_STAGE;
        {
            const float* rowp = (const float*)(smem + (it & 1) * F_STAGE + F_A32) + crow * 40 + cko;
            uint32_t hq[4];
            #pragma unroll
            for (int e = 0; e < 4; e++) hq[e] = pack2(rowp[e*2], rowp[e*2+1]);
            *(uint4*)(smem + F_CONV + crow * 80 + cko * 2) = make_uint4(hq[0], hq[1], hq[2], hq[3]);
        }
        __syncthreads();
        #pragma unroll
        for (int s = 0; s < 2; s++) {
            const int kc = s * 16;
            uint32_t fA[2][4];
            #pragma unroll
            for (int mf = 0; mf < 2; mf++) {
                uint32_t off = (uint32_t)(((wm * 32 + mf * 16 + lrow) * 40 + kc + lk) * 2);
                LDSM4(fA[mf][0], fA[mf][1], fA[mf][2], fA[mf][3], sb + F_CONV + off);
            }
            uint32_t fB[6][2];
            #pragma unroll
            for (int q = 0; q < 3; q++) {
                uint32_t off = (uint32_t)(((wn * 48 + q * 16 + lrow) * 40 + kc + lk) * 2);
                uint32_t r0, r1, r2, r3;
                LDSM4(r0, r1, r2, r3, bufb + F_B + off);
                fB[q*2][0] = r0; fB[q*2][1] = r2;
                fB[q*2+1][0] = r1; fB[q*2+1][1] = r3;
            }
            #pragma unroll
            for (int mf = 0; mf < 2; mf++)
                #pragma unroll
                for (int nf = 0; nf < 6; nf++)
                    MMA16816(acc[mf][nf], fA[mf][0], fA[mf][1], fA[mf][2], fA[mf][3],
                             fB[nf][0], fB[nf][1]);
        }
        __syncthreads();
        // 2-stage: prefetch next stage + a gather chunk AFTER compute (WAR safety)
        if (it + 2 < 4) issue(it + 2, it & 1);
        gather(it);
        CP_COMMIT();
    }

    CP_WAIT0();          // all gathers landed
    __syncthreads();

    // epilogue: acc += sum_k w_k * P_gathered (from smem); write fp16 h1 + GN1 stats
    const int g = lane >> 2, tig = lane & 3;
    float gs[16];
    #pragma unroll
    for (int i = 0; i < 16; i++) gs[i] = 0.0f;
    #pragma unroll
    for (int mf = 0; mf < 2; mf++) {
        int rl = wm * 32 + mf * 16 + g;
        float wa0 = s_wt[rl * 3 + 0], wa1 = s_wt[rl * 3 + 1], wa2 = s_wt[rl * 3 + 2];
        float wb0 = s_wt[(rl + 8) * 3 + 0], wb1 = s_wt[(rl + 8) * 3 + 1], wb2 = s_wt[(rl + 8) * 3 + 2];
        #pragma unroll
        for (int nf = 0; nf < 6; nf++) {
            int col = wn * 48 + nf * 8 + tig * 2;
            float2 p0a = __half22float2(*(__half2*)(smem + F_G +      0 + rl * 384 + col * 2));
            float2 p1a = __half22float2(*(__half2*)(smem + F_G +  49152 + rl * 384 + col * 2));
            float2 p2a = __half22float2(*(__half2*)(smem + F_G +  98304 + rl * 384 + col * 2));
            float2 p0b = __half22float2(*(__half2*)(smem + F_G +      0 + (rl + 8) * 384 + col * 2));
            float2 p1b = __half22float2(*(__half2*)(smem + F_G +  49152 + (rl + 8) * 384 + col * 2));
            float2 p2b = __half22float2(*(__half2*)(smem + F_G +  98304 + (rl + 8) * 384 + col * 2));
            float d0 = acc[mf][nf][0] + wa0 * p0a.x + wa1 * p1a.x + wa2 * p2a.x;
            float d1 = acc[mf][nf][1] + wa0 * p0a.y + wa1 * p1a.y + wa2 * p2a.y;
            float d2 = acc[mf][nf][2] + wb0 * p0b.x + wb1 * p1b.x + wb2 * p2b.x;
            float d3 = acc[mf][nf][3] + wb0 * p0b.y + wb1 * p1b.y + wb2 * p2b.y;
            int row = m0 + rl;
            *(uint32_t*)(C + (size_t)row * CMID + col)       = pack2(d0, d1);
            *(uint32_t*)(C + (size_t)(row + 8) * CMID + col) = pack2(d2, d3);
            int grp = col / 24;
            gs[grp]     += d0 + d1 + d2 + d3;
            gs[8 + grp] += d0*d0 + d1*d1 + d2*d2 + d3*d3;
        }
    }
    __syncthreads();
    float* red = (float*)smem;            // stage area is dead
    #pragma unroll
    for (int i = 0; i < 16; i++) red[i * 512 + tid] = gs[i];
    __syncthreads();
    for (int off = 256; off > 0; off >>= 1) {
        if (tid < off) {
            #pragma unroll
            for (int i = 0; i < 16; i++) red[i * 512 + tid] += red[i * 512 + tid + off];
        }
        __syncthreads();
    }
    if (tid < 16) {
        int cta = blockIdx.x & 127;
        int grp = tid & 7;
        part[(tid >= 8 ? 4096 : 0) + (bb * 8 + grp) * 128 + cta] = red[tid * 512];
    }
}

// ==================== GEMM2: single-term fp16 (h1 fp16 in), 512 thr, 3-stage ====================
#define G2_A16 0
#define G2_B   10240
#define G2_STAGE 20480
#define G2_CAH (3 * G2_STAGE)
#define G2_AFF (G2_CAH + 10240)
#define G2_SMEM (G2_AFF + 2 * CMID * 4)

__global__ void __launch_bounds__(512) gemm2_mma(
    const __half* __restrict__ H, const __half* __restrict__ Bh,
    const float* __restrict__ a1, const float* __restrict__ b1,
    float* __restrict__ Out, float* __restrict__ part)
{
    extern __shared__ char smem[];
    const uint32_t sb = smem_u32(smem);
    const int tid = threadIdx.x, lane = tid & 31, wid = tid >> 5;
    const int wm = wid & 3, wn = wid >> 2;
    const int m0 = blockIdx.x * 128;
    const int bb = blockIdx.x >> 7;

    float* s_a = (float*)(smem + G2_AFF);
    float* s_b = s_a + CMID;
    for (int i = tid; i < CMID; i += 512) { s_a[i] = a1[bb * CMID + i]; s_b[i] = b1[bb * CMID + i]; }

    auto issue = [&](int it, int buf) {
        const int kc0 = it * 32;
        const uint32_t base = sb + buf * G2_STAGE;
        {
            int row = tid >> 2, ko = (tid & 3) * 8;
            CP16(base + G2_A16 + row * 80 + ko * 2, H + (size_t)(m0 + row) * CMID + kc0 + ko);
        }
        {
            int row = tid >> 2, ko = (tid & 3) * 8;
            CP16(base + G2_B + row * 80 + ko * 2, Bh + (size_t)row * CMID + kc0 + ko);
        }
    };

    float acc[2][4][4];
    #pragma unroll
    for (int i = 0; i < 2; i++)
        #pragma unroll
        for (int j = 0; j < 4; j++)
            #pragma unroll
            for (int k = 0; k < 4; k++) acc[i][j][k] = 0.0f;

    __syncthreads();
    issue(0, 0); CP_COMMIT();
    issue(1, 1); CP_COMMIT();

    const int crow = tid >> 2, cko = (tid & 3) * 8;
    const int lrow = lane & 15, lk = (lane >> 4) * 8;
    for (int it = 0; it < 6; it++) {
        CP_WAIT1();
        __syncthreads();
        if (it + 2 < 6) issue(it + 2, (it + 2) % 3);   // 3-stage: safe
        CP_COMMIT();
        const uint32_t bufb = sb + (it % 3) * G2_STAGE;
        {
            const int kc0 = it * 32;
            uint4 rw = *(const uint4*)(smem + (it % 3) * G2_STAGE + G2_A16 + crow * 80 + cko * 2);
            uint32_t parts[4] = { rw.x, rw.y, rw.z, rw.w };
            uint32_t hq[4];
            #pragma unroll
            for (int e = 0; e < 4; e++) {
                __half2 hp = *reinterpret_cast<__half2*>(&parts[e]);
                int c = kc0 + cko + e * 2;
                float x = fmaxf(fmaf(__low2float(hp),  s_a[c],   s_b[c]),   0.0f);
                float y = fmaxf(fmaf(__high2float(hp), s_a[c+1], s_b[c+1]), 0.0f);
                hq[e] = pack2(x, y);
            }
            *(uint4*)(smem + G2_CAH + crow * 80 + cko * 2) = make_uint4(hq[0], hq[1], hq[2], hq[3]);
        }
        __syncthreads();
        #pragma unroll
        for (int s = 0; s < 2; s++) {
            const int kc = s * 16;
            uint32_t fA[2][4];
            #pragma unroll
            for (int mf = 0; mf < 2; mf++) {
                uint32_t off = (uint32_t)(((wm * 32 + mf * 16 + lrow) * 40 + kc + lk) * 2);
                LDSM4(fA[mf][0], fA[mf][1], fA[mf][2], fA[mf][3], sb + G2_CAH + off);
            }
            uint32_t fB[4][2];
            #pragma unroll
            for (int q = 0; q < 2; q++) {
                uint32_t off = (uint32_t)(((wn * 32 + q * 16 + lrow) * 40 + kc + lk) * 2);
                uint32_t r0, r1, r2, r3;
                LDSM4(r0, r1, r2, r3, bufb + G2_B + off);
                fB[q*2][0] = r0; fB[q*2][1] = r2;
                fB[q*2+1][0] = r1; fB[q*2+1][1] = r3;
            }
            #pragma unroll
            for (int mf = 0; mf < 2; mf++)
                #pragma unroll
                for (int nf = 0; nf < 4; nf++)
                    MMA16816(acc[mf][nf], fA[mf][0], fA[mf][1], fA[mf][2], fA[mf][3],
                             fB[nf][0], fB[nf][1]);
        }
        __syncthreads();
    }

    const int g = lane >> 2, tig = lane & 3;
    float gs[16];
    #pragma unroll
    for (int i = 0; i < 16; i++) gs[i] = 0.0f;
    #pragma unroll
    for (int mf = 0; mf < 2; mf++)
        #pragma unroll
        for (int nf = 0; nf < 4; nf++) {
            int row = m0 + wm * 32 + mf * 16 + g;
            int col = wn * 32 + nf * 8 + tig * 2;
            float d0 = acc[mf][nf][0], d1 = acc[mf][nf][1];
            float d2 = acc[mf][nf][2], d3 = acc[mf][nf][3];
            *(float2*)(Out + (size_t)row * COUT + col)       = make_float2(d0, d1);
            *(float2*)(Out + (size_t)(row + 8) * COUT + col) = make_float2(d2, d3);
            int grp = col >> 4;
            gs[grp]     += d0 + d1 + d2 + d3;
            gs[8 + grp] += d0*d0 + d1*d1 + d2*d2 + d3*d3;
        }
    __syncthreads();
    float* red = (float*)smem;
    #pragma unroll
    for (int i = 0; i < 16; i++) red[i * 512 + tid] = gs[i];
    __syncthreads();
    for (int off = 256; off > 0; off >>= 1) {
        if (tid < off) {
            #pragma unroll
            for (int i = 0; i < 16; i++) red[i * 512 + tid] += red[i * 512 + tid + off];
        }
        __syncthreads();
    }
    if (tid < 16) {
        int cta = blockIdx.x & 127;
        int grp = tid & 7;
        part[(tid >= 8 ? 4096 : 0) + (bb * 8 + grp) * 128 + cta] = red[tid * 512];
    }
}

// ==================== GN final: parallel 128-thread reduce ====================
template<int CPG>
__global__ void __launch_bounds__(128) stats_final(
    const float* __restrict__ ps, const float* __restrict__ pss,
    const float* __restrict__ gamma, const float* __restrict__ beta,
    float* __restrict__ ac, float* __restrict__ bc, int Cdim)
{
    const int bg = blockIdx.x;
    const int b = bg >> 3, g = bg & 7;
    const int tid = threadIdx.x, lane = tid & 31, wrp = tid >> 5;
    __shared__ float sh[8];
    __shared__ float s_m, s_i;

    float s = ps[bg * 128 + tid], ss = pss[bg * 128 + tid];
    #pragma unroll
    for (int off = 16; off > 0; off >>= 1) {
        s  += __shfl_down_sync(0xFFFFFFFF, s,  off);
        ss += __shfl_down_sync(0xFFFFFFFF, ss, off);
    }
    if (lane == 0) { sh[wrp] = s; sh[4 + wrp] = ss; }
    __syncthreads();
    if (tid == 0) {
        float ts  = sh[0] + sh[1] + sh[2] + sh[3];
        float tss = sh[4] + sh[5] + sh[6] + sh[7];
        float cnt = (float)NPTS * (float)CPG;
        float mu  = ts / cnt;
        float var = tss / cnt - mu * mu;
        s_m = mu; s_i = rsqrtf(var + EPS_GN);
    }
    __syncthreads();
    if (tid < CPG) {
        int ch = g * CPG + tid;
        float a = gamma[ch] * s_i;
        ac[b * Cdim + ch] = a;
        bc[b * Cdim + ch] = beta[ch] - s_m * a;
    }
}

// ==================== finalize: vectorized float4 ====================
__global__ void __launch_bounds__(256) finalize_kernel(
    float* __restrict__ out, const float* __restrict__ a, const float* __restrict__ bc)
{
    size_t i4 = (size_t)blockIdx.x * 256 + threadIdx.x;
    int c0 = (int)(i4 & 31) * 4;
    int b  = (int)(i4 >> 19);
    const float* ap = a  + b * COUT + c0;
    const float* bp = bc + b * COUT + c0;
    float4 v = ((float4*)out)[i4];
    v.x = fmaxf(fmaf(v.x, ap[0], bp[0]), 0.0f);
    v.y = fmaxf(fmaf(v.y, ap[1], bp[1]), 0.0f);
    v.z = fmaxf(fmaf(v.z, ap[2], bp[2]), 0.0f);
    v.w = fmaxf(fmaf(v.w, ap[3], bp[3]), 0.0f);
    ((float4*)out)[i4] = v;
}

// ==================== launch ====================
extern "C" void kernel_launch(void* const* d_in, const int* in_sizes, int n_in,
                              void* d_out, int out_size)
{
    const float* fine_xyz    = (const float*)d_in[0];
    const float* coarse_xyz  = (const float*)d_in[1];
    const float* fine_feat   = (const float*)d_in[2];
    const float* coarse_feat = (const float*)d_in[3];
    const float* w1          = (const float*)d_in[4];
    const float* g1_w        = (const float*)d_in[5];
    const float* g1_b        = (const float*)d_in[6];
    const float* w2          = (const float*)d_in[7];
    const float* g2_w        = (const float*)d_in[8];
    const float* g2_b        = (const float*)d_in[9];
    float* out = (float*)d_out;

    __half *h1, *Pm, *w1h, *w2h;
    float *wt, *part1, *part2, *a1, *b1, *a2, *b2;
    int* idx;
    cudaGetSymbolAddress((void**)&h1, g_h1);
    cudaGetSymbolAddress((void**)&Pm, g_P);
    cudaGetSymbolAddress((void**)&idx, g_idx);
    cudaGetSymbolAddress((void**)&wt, g_wt);
    cudaGetSymbolAddress((void**)&w1h, g_w1h);
    cudaGetSymbolAddress((void**)&w2h, g_w2h);
    cudaGetSymbolAddress((void**)&part1, g_part1);
    cudaGetSymbolAddress((void**)&part2, g_part2);
    cudaGetSymbolAddress((void**)&a1, g_a1);
    cudaGetSymbolAddress((void**)&b1, g_b1);
    cudaGetSymbolAddress((void**)&a2, g_a2);
    cudaGetSymbolAddress((void**)&b2, g_b2);

    cudaFuncSetAttribute(pgemm_mma, cudaFuncAttributeMaxDynamicSharedMemorySize, P_SMEM);
    cudaFuncSetAttribute(gemm1_mma, cudaFuncAttributeMaxDynamicSharedMemorySize, F_SMEM);
    cudaFuncSetAttribute(gemm2_mma, cudaFuncAttributeMaxDynamicSharedMemorySize, G2_SMEM);

    knn_kernel<<<dim3(NPTS / 128, BATCH), 128>>>(fine_xyz, coarse_xyz, idx, wt);
    prep_weights<<<(CMID * CIN + COUT * CMID + 255) / 256, 256>>>(w1, w2, w1h, w2h);
    pgemm_mma<<<BATCH * (SPTS / 128), 512, P_SMEM>>>(coarse_feat, w1h, Pm);
    gemm1_mma<<<BN_TOTAL / 128, 512, F_SMEM>>>(fine_feat, Pm, idx, wt, w1h, h1, part1);
    stats_final<CMID / GROUPS><<<BATCH * GROUPS, 128>>>(part1, part1 + 4096, g1_w, g1_b, a1, b1, CMID);
    gemm2_mma<<<BN_TOTAL / 128, 512, G2_SMEM>>>(h1, w2h, a1, b1, out, part2);
    stats_final<COUT / GROUPS><<<BATCH * GROUPS, 128>>>(part2, part2 + 4096, g2_w, g2_b, a2, b2, COUT);
    finalize_kernel<<<(BN_TOTAL * COUT / 4) / 256, 256>>>(out, a2, b2);
}

// round 17
// speedup vs baseline: 1.0553x; 1.0553x over previous
#include <cuda_runtime.h>
#include <cuda_fp16.h>
#include <cstdint>
#include <cstddef>

// Problem constants
#define BATCH 4
#define NPTS  16384
#define SPTS  4096
#define CF    128
#define CC    256
#define CIN   384
#define CMID  192
#define COUT  128
#define GROUPS 8
#define EPS_GN 1e-5f
#define EPS_D  1e-8f
#define BN_TOTAL (BATCH * NPTS)   // 65536
#define CTAS_PER_BATCH 128

// -------------------- scratch (device globals; no allocation) --------------------
__device__ __align__(16) __half g_h1[(size_t)BN_TOTAL * CMID];        // 25 MB
__device__ __align__(16) __half g_P[(size_t)BATCH * SPTS * CMID];     // 6.3 MB
__device__ int   g_idx[(size_t)BN_TOTAL * 3];
__device__ float g_wt[(size_t)BN_TOTAL * 3];
__device__ __align__(16) __half g_w1h[CMID * CIN];
__device__ __align__(16) __half g_w2h[COUT * CMID];
__device__ float g_part1[2 * 32 * CTAS_PER_BATCH];
__device__ float g_part2[2 * 32 * CTAS_PER_BATCH];
__device__ float g_a1[BATCH * CMID], g_b1[BATCH * CMID];
__device__ float g_a2[BATCH * COUT], g_b2[BATCH * COUT];

// ==================== helpers ====================
__device__ __forceinline__ uint32_t smem_u32(const void* p) {
    uint32_t a;
    asm("{ .reg .u64 t; cvta.to.shared.u64 t, %1; cvt.u32.u64 %0, t; }" : "=r"(a) : "l"(p));
    return a;
}
#define LDSM4(r0, r1, r2, r3, addr) \
    asm volatile("ldmatrix.sync.aligned.m8n8.x4.shared.b16 {%0,%1,%2,%3}, [%4];" \
        : "=r"(r0), "=r"(r1), "=r"(r2), "=r"(r3) : "r"(addr))
#define MMA16816(d, a0, a1, a2, a3, b0, b1) \
    asm volatile("mma.sync.aligned.m16n8k16.row.col.f32.f16.f16.f32 " \
        "{%0,%1,%2,%3},{%4,%5,%6,%7},{%8,%9},{%0,%1,%2,%3};" \
        : "+f"((d)[0]), "+f"((d)[1]), "+f"((d)[2]), "+f"((d)[3]) \
        : "r"(a0), "r"(a1), "r"(a2), "r"(a3), "r"(b0), "r"(b1))
#define CP16(dst, src) \
    asm volatile("cp.async.cg.shared.global [%0], [%1], 16;" :: "r"(dst), "l"(src))
#define CP_COMMIT() asm volatile("cp.async.commit_group;" ::: "memory")
#define CP_WAIT1()  asm volatile("cp.async.wait_group 1;" ::: "memory")

__device__ __forceinline__ uint32_t pack2(float x, float y) {
    __half hx = __float2half_rn(x), hy = __float2half_rn(y);
    return ((uint32_t)__half_as_ushort(hy) << 16) | __half_as_ushort(hx);
}

// ==================== Kernel 1: kNN (K=3) + IDW weights (256 thr/block) ====================
#define KNN_CHUNK 2048
__global__ void __launch_bounds__(256) knn_kernel(
    const float* __restrict__ fxyz, const float* __restrict__ cxyz,
    int* __restrict__ oidx, float* __restrict__ owt)
{
    __shared__ float4 cs[KNN_CHUNK];
    const int b = blockIdx.y;
    const int n = blockIdx.x * 256 + threadIdx.x;
    const float* fp = fxyz + ((size_t)b * NPTS + n) * 3;
    const float qx = fp[0], qy = fp[1], qz = fp[2];

    float s0 = 3.4e38f, s1 = 3.4e38f, s2 = 3.4e38f;
    int   i0 = 0, i1 = 0, i2 = 0;

    auto insert = [&](float sc, int iv) {
        if (sc < s1) {
            s2 = s1; i2 = i1;
            if (sc < s0) { s1 = s0; i1 = i0; s0 = sc; i0 = iv; }
            else         { s1 = sc; i1 = iv; }
        } else { s2 = sc; i2 = iv; }
    };

    for (int c0 = 0; c0 < SPTS; c0 += KNN_CHUNK) {
        __syncthreads();
        for (int j = threadIdx.x; j < KNN_CHUNK; j += 256) {
            const float* cp = cxyz + ((size_t)b * SPTS + c0 + j) * 3;
            float x = cp[0], y = cp[1], z = cp[2];
            cs[j] = make_float4(-2.0f * x, -2.0f * y, -2.0f * z, x*x + y*y + z*z);
        }
        __syncthreads();
        // score = ||c||^2 - 2 q.c (reference score minus per-thread const ||q||^2)
        #pragma unroll 4
        for (int j = 0; j < KNN_CHUNK; j += 2) {
            float4 ca = cs[j], cb = cs[j + 1];
            float sa  = fmaf(qx, ca.x, fmaf(qy, ca.y, fmaf(qz, ca.z, ca.w)));
            float sb2 = fmaf(qx, cb.x, fmaf(qy, cb.y, fmaf(qz, cb.z, cb.w)));
            if (fminf(sa, sb2) < s2) {
                if (sa  < s2) insert(sa,  c0 + j);
                if (sb2 < s2) insert(sb2, c0 + j + 1);
            }
        }
    }
    int ii[3] = { i0, i1, i2 };
    float w[3], wsum = 0.0f;
    #pragma unroll
    for (int k = 0; k < 3; k++) {
        const float* cp = cxyz + ((size_t)b * SPTS + ii[k]) * 3;
        float dx = qx - cp[0], dy = qy - cp[1], dz = qz - cp[2];
        float d2 = fmaxf(dx*dx + dy*dy + dz*dz, EPS_D);
        w[k] = 1.0f / d2; wsum += w[k];
    }
    float inv = 1.0f / wsum;
    size_t base = ((size_t)b * NPTS + n) * 3;
    #pragma unroll
    for (int k = 0; k < 3; k++) { oidx[base + k] = ii[k]; owt[base + k] = w[k] * inv; }
}

// ==================== Kernel 2: weights -> fp16 ====================
__global__ void prep_weights(const float* __restrict__ w1, const float* __restrict__ w2,
                             __half* w1h, __half* w2h)
{
    int i = blockIdx.x * 256 + threadIdx.x;
    if (i < CMID * CIN) w1h[i] = __float2half_rn(w1[i]);
    int j = i - CMID * CIN;
    if (j >= 0 && j < COUT * CMID) w2h[j] = __float2half_rn(w2[j]);
}

// ==================== P-GEMM: P[b,s,:] = cfeat[b,s,:] @ W1coarse^T ====================
#define P_A32 0
#define P_B   20480
#define P_STAGE 35840
#define P_CONV (3 * P_STAGE)            // 107520
#define P_SMEM (P_CONV + 10240)         // 117760

__global__ void __launch_bounds__(512) pgemm_mma(
    const float* __restrict__ cfeat, const __half* __restrict__ Bw,
    __half* __restrict__ P)
{
    extern __shared__ char smem[];
    const uint32_t sb = smem_u32(smem);
    const int tid = threadIdx.x, lane = tid & 31, wid = tid >> 5;
    const int wm = wid & 3, wn = wid >> 2;
    const int bb = blockIdx.x >> 5;
    const int m0 = (blockIdx.x & 31) * 128;

    auto issue = [&](int it, int buf) {
        const int kc0 = it * 32;
        const uint32_t base = sb + buf * P_STAGE;
        #pragma unroll
        for (int u = 0; u < 2; u++) {
            int i = u * 512 + tid;
            int row = i >> 3, ko = (i & 7) * 4;
            CP16(base + P_A32 + row * 160 + ko * 4,
                 cfeat + ((size_t)bb * SPTS + m0 + row) * CC + kc0 + ko);
        }
        #pragma unroll
        for (int q = 0; q < 2; q++) {
            int i = q * 512 + tid;
            if (i < 768) {
                int row = i >> 2, ko = (i & 3) * 8;
                CP16(base + P_B + row * 80 + ko * 2, Bw + (size_t)row * CIN + 128 + kc0 + ko);
            }
        }
    };

    float acc[2][6][4];
    #pragma unroll
    for (int i = 0; i < 2; i++)
        #pragma unroll
        for (int j = 0; j < 6; j++)
            #pragma unroll
            for (int k = 0; k < 4; k++) acc[i][j][k] = 0.0f;

    issue(0, 0); CP_COMMIT();
    issue(1, 1); CP_COMMIT();

    const int crow = tid >> 2, cko = (tid & 3) * 8;
    const int lrow = lane & 15, lk = (lane >> 4) * 8;
    for (int it = 0; it < 8; it++) {
        CP_WAIT1();
        __syncthreads();
        if (it + 2 < 8) issue(it + 2, (it + 2) % 3);   // 3-stage: safe before compute
        CP_COMMIT();
        const uint32_t bufb = sb + (it % 3) * P_STAGE;
        {
            const float* rowp = (const float*)(smem + (it % 3) * P_STAGE + P_A32) + crow * 40 + cko;
            uint32_t hq[4];
            #pragma unroll
            for (int e = 0; e < 4; e++) hq[e] = pack2(rowp[e*2], rowp[e*2+1]);
            *(uint4*)(smem + P_CONV + crow * 80 + cko * 2) = make_uint4(hq[0], hq[1], hq[2], hq[3]);
        }
        __syncthreads();
        #pragma unroll
        for (int s = 0; s < 2; s++) {
            const int kc = s * 16;
            uint32_t fA[2][4];
            #pragma unroll
            for (int mf = 0; mf < 2; mf++) {
                uint32_t off = (uint32_t)(((wm * 32 + mf * 16 + lrow) * 40 + kc + lk) * 2);
                LDSM4(fA[mf][0], fA[mf][1], fA[mf][2], fA[mf][3], sb + P_CONV + off);
            }
            uint32_t fB[6][2];
            #pragma unroll
            for (int q = 0; q < 3; q++) {
                uint32_t off = (uint32_t)(((wn * 48 + q * 16 + lrow) * 40 + kc + lk) * 2);
                uint32_t r0, r1, r2, r3;
                LDSM4(r0, r1, r2, r3, bufb + P_B + off);
                fB[q*2][0] = r0; fB[q*2][1] = r2;
                fB[q*2+1][0] = r1; fB[q*2+1][1] = r3;
            }
            #pragma unroll
            for (int mf = 0; mf < 2; mf++)
                #pragma unroll
                for (int nf = 0; nf < 6; nf++)
                    MMA16816(acc[mf][nf], fA[mf][0], fA[mf][1], fA[mf][2], fA[mf][3],
                             fB[nf][0], fB[nf][1]);
        }
        __syncthreads();
    }

    const int g = lane >> 2, tig = lane & 3;
    #pragma unroll
    for (int mf = 0; mf < 2; mf++)
        #pragma unroll
        for (int nf = 0; nf < 6; nf++) {
            int row = m0 + wm * 32 + mf * 16 + g;
            int col = wn * 48 + nf * 8 + tig * 2;
            size_t base = ((size_t)bb * SPTS + row) * CMID + col;
            *(uint32_t*)(P + base)              = pack2(acc[mf][nf][0], acc[mf][nf][1]);
            *(uint32_t*)(P + base + 8 * CMID)   = pack2(acc[mf][nf][2], acc[mf][nf][3]);
        }
}

// ==================== GEMM1 (K=128 fine) + P-gather epilogue + GN1 stats (R15) ====================
// h1 = fine_feat @ W1fine^T + sum_k w_k * P[idx_k]
#define F_A32 0
#define F_B   20480
#define F_STAGE 35840                   // A32 20480 + B 15360
#define F_CONV (2 * F_STAGE)            // 71680 (10240)
#define F_PS   (F_CONV + 10240)         // 81920: PS fp32 128x192 = 98304
#define F_IDX  (F_PS + 98304)           // 180224 (1536)
#define F_WT   (F_IDX + 1536)           // 181760 (1536)
#define F_SMEM (F_WT + 1536)            // 183296

__global__ void __launch_bounds__(512) gemm1_mma(
    const float* __restrict__ ffeat, const __half* __restrict__ Pm,
    const int* __restrict__ idx, const float* __restrict__ wt,
    const __half* __restrict__ Bw,
    __half* __restrict__ C, float* __restrict__ part)
{
    extern __shared__ char smem[];
    const uint32_t sb = smem_u32(smem);
    const int tid = threadIdx.x, lane = tid & 31, wid = tid >> 5;
    const int wm = wid & 3, wn = wid >> 2;
    const int m0 = blockIdx.x * 128;
    const int bb = blockIdx.x >> 7;

    int*   s_idx = (int*)(smem + F_IDX);
    float* s_wt  = (float*)(smem + F_WT);
    if (tid < 384) {
        int row = tid / 3, k = tid - row * 3;
        s_idx[tid] = idx[((size_t)(m0 + row)) * 3 + k];
        s_wt[tid]  = wt[((size_t)(m0 + row)) * 3 + k];
    }

    auto issue = [&](int it, int buf) {
        const int kc0 = it * 32;
        const uint32_t base = sb + buf * F_STAGE;
        #pragma unroll
        for (int u = 0; u < 2; u++) {     // A32: 1024 CP16 (fine_feat)
            int i = u * 512 + tid;
            int row = i >> 3, ko = (i & 7) * 4;
            CP16(base + F_A32 + row * 160 + ko * 4,
                 ffeat + (size_t)(m0 + row) * CF + kc0 + ko);
        }
        #pragma unroll
        for (int q = 0; q < 2; q++) {     // B: 768 CP16 (w1h cols 0..127)
            int i = q * 512 + tid;
            if (i < 768) {
                int row = i >> 2, ko = (i & 3) * 8;
                CP16(base + F_B + row * 80 + ko * 2, Bw + (size_t)row * CIN + kc0 + ko);
            }
        }
    };

    float acc[2][6][4];
    #pragma unroll
    for (int i = 0; i < 2; i++)
        #pragma unroll
        for (int j = 0; j < 6; j++)
            #pragma unroll
            for (int k = 0; k < 4; k++) acc[i][j][k] = 0.0f;

    __syncthreads();     // s_idx/s_wt visible
    issue(0, 0); CP_COMMIT();
    issue(1, 1); CP_COMMIT();

    const int crow = tid >> 2, cko = (tid & 3) * 8;
    const int lrow = lane & 15, lk = (lane >> 4) * 8;
    for (int it = 0; it < 4; it++) {
        CP_WAIT1();
        __syncthreads();
        const uint32_t bufb = sb + (it & 1) * F_STAGE;
        {
            const float* rowp = (const float*)(smem + (it & 1) * F_STAGE + F_A32) + crow * 40 + cko;
            uint32_t hq[4];
            #pragma unroll
            for (int e = 0; e < 4; e++) hq[e] = pack2(rowp[e*2], rowp[e*2+1]);
            *(uint4*)(smem + F_CONV + crow * 80 + cko * 2) = make_uint4(hq[0], hq[1], hq[2], hq[3]);
        }
        __syncthreads();
        #pragma unroll
        for (int s = 0; s < 2; s++) {
            const int kc = s * 16;
            uint32_t fA[2][4];
            #pragma unroll
            for (int mf = 0; mf < 2; mf++) {
                uint32_t off = (uint32_t)(((wm * 32 + mf * 16 + lrow) * 40 + kc + lk) * 2);
                LDSM4(fA[mf][0], fA[mf][1], fA[mf][2], fA[mf][3], sb + F_CONV + off);
            }
            uint32_t fB[6][2];
            #pragma unroll
            for (int q = 0; q < 3; q++) {
                uint32_t off = (uint32_t)(((wn * 48 + q * 16 + lrow) * 40 + kc + lk) * 2);
                uint32_t r0, r1, r2, r3;
                LDSM4(r0, r1, r2, r3, bufb + F_B + off);
                fB[q*2][0] = r0; fB[q*2][1] = r2;
                fB[q*2+1][0] = r1; fB[q*2+1][1] = r3;
            }
            #pragma unroll
            for (int mf = 0; mf < 2; mf++)
                #pragma unroll
                for (int nf = 0; nf < 6; nf++)
                    MMA16816(acc[mf][nf], fA[mf][0], fA[mf][1], fA[mf][2], fA[mf][3],
                             fB[nf][0], fB[nf][1]);
        }
        __syncthreads();
        // 2-stage: prefetch ONLY after compute on buffer (it&1) is done (WAR safety)
        if (it + 2 < 4) issue(it + 2, it & 1);
        CP_COMMIT();                 // empty group at drain keeps the count aligned
    }

    // PS tile: PS[r][c] = sum_k w_k * P[idx_k(r)][c]  (fp32, smem)
    float* PS = (float*)(smem + F_PS);
    for (int i = tid; i < 128 * 24; i += 512) {     // 24 chunks of 8 cols per row
        int r = i / 24, cch = i - (i / 24) * 24;
        float w0 = s_wt[r * 3 + 0], w1v = s_wt[r * 3 + 1], w2v = s_wt[r * 3 + 2];
        const __half* P0 = Pm + ((size_t)bb * SPTS + s_idx[r * 3 + 0]) * CMID + cch * 8;
        const __half* P1 = Pm + ((size_t)bb * SPTS + s_idx[r * 3 + 1]) * CMID + cch * 8;
        const __half* P2 = Pm + ((size_t)bb * SPTS + s_idx[r * 3 + 2]) * CMID + cch * 8;
        uint4 u0 = *(const uint4*)P0, u1 = *(const uint4*)P1, u2 = *(const uint4*)P2;
        const __half2* h0 = (const __half2*)&u0;
        const __half2* h1p = (const __half2*)&u1;
        const __half2* h2 = (const __half2*)&u2;
        float* dst = PS + r * 192 + cch * 8;
        #pragma unroll
        for (int e = 0; e < 4; e++) {
            float2 f0 = __half22float2(h0[e]);
            float2 f1 = __half22float2(h1p[e]);
            float2 f2 = __half22float2(h2[e]);
            dst[e*2]   = w0 * f0.x + w1v * f1.x + w2v * f2.x;
            dst[e*2+1] = w0 * f0.y + w1v * f1.y + w2v * f2.y;
        }
    }
    __syncthreads();

    // epilogue: acc += PS; write fp16 h1 + GN1 partial stats
    const int g = lane >> 2, tig = lane & 3;
    float gs[16];
    #pragma unroll
    for (int i = 0; i < 16; i++) gs[i] = 0.0f;
    #pragma unroll
    for (int mf = 0; mf < 2; mf++)
        #pragma unroll
        for (int nf = 0; nf < 6; nf++) {
            int rl = wm * 32 + mf * 16 + g;
            int col = wn * 48 + nf * 8 + tig * 2;
            float d0 = acc[mf][nf][0] + PS[rl * 192 + col];
            float d1 = acc[mf][nf][1] + PS[rl * 192 + col + 1];
            float d2 = acc[mf][nf][2] + PS[(rl + 8) * 192 + col];
            float d3 = acc[mf][nf][3] + PS[(rl + 8) * 192 + col + 1];
            int row = m0 + rl;
            *(uint32_t*)(C + (size_t)row * CMID + col)       = pack2(d0, d1);
            *(uint32_t*)(C + (size_t)(row + 8) * CMID + col) = pack2(d2, d3);
            int grp = col / 24;
            gs[grp]     += d0 + d1 + d2 + d3;
            gs[8 + grp] += d0*d0 + d1*d1 + d2*d2 + d3*d3;
        }
    __syncthreads();
    float* red = (float*)smem;            // stage area is dead
    #pragma unroll
    for (int i = 0; i < 16; i++) red[i * 512 + tid] = gs[i];
    __syncthreads();
    for (int off = 256; off > 0; off >>= 1) {
        if (tid < off) {
            #pragma unroll
            for (int i = 0; i < 16; i++) red[i * 512 + tid] += red[i * 512 + tid + off];
        }
        __syncthreads();
    }
    if (tid < 16) {
        int cta = blockIdx.x & 127;
        int grp = tid & 7;
        part[(tid >= 8 ? 4096 : 0) + (bb * 8 + grp) * 128 + cta] = red[tid * 512];
    }
}

// ==================== GEMM2: single-term fp16 (h1 fp16 in), 512 thr, 3-stage ====================
#define G2_A16 0
#define G2_B   10240
#define G2_STAGE 20480
#define G2_CAH (3 * G2_STAGE)
#define G2_AFF (G2_CAH + 10240)
#define G2_SMEM (G2_AFF + 2 * CMID * 4)

__global__ void __launch_bounds__(512) gemm2_mma(
    const __half* __restrict__ H, const __half* __restrict__ Bh,
    const float* __restrict__ a1, const float* __restrict__ b1,
    float* __restrict__ Out, float* __restrict__ part)
{
    extern __shared__ char smem[];
    const uint32_t sb = smem_u32(smem);
    const int tid = threadIdx.x, lane = tid & 31, wid = tid >> 5;
    const int wm = wid & 3, wn = wid >> 2;
    const int m0 = blockIdx.x * 128;
    const int bb = blockIdx.x >> 7;

    float* s_a = (float*)(smem + G2_AFF);
    float* s_b = s_a + CMID;
    for (int i = tid; i < CMID; i += 512) { s_a[i] = a1[bb * CMID + i]; s_b[i] = b1[bb * CMID + i]; }

    auto issue = [&](int it, int buf) {
        const int kc0 = it * 32;
        const uint32_t base = sb + buf * G2_STAGE;
        {
            int row = tid >> 2, ko = (tid & 3) * 8;
            CP16(base + G2_A16 + row * 80 + ko * 2, H + (size_t)(m0 + row) * CMID + kc0 + ko);
        }
        {
            int row = tid >> 2, ko = (tid & 3) * 8;
            CP16(base + G2_B + row * 80 + ko * 2, Bh + (size_t)row * CMID + kc0 + ko);
        }
    };

    float acc[2][4][4];
    #pragma unroll
    for (int i = 0; i < 2; i++)
        #pragma unroll
        for (int j = 0; j < 4; j++)
            #pragma unroll
            for (int k = 0; k < 4; k++) acc[i][j][k] = 0.0f;

    __syncthreads();
    issue(0, 0); CP_COMMIT();
    issue(1, 1); CP_COMMIT();

    const int crow = tid >> 2, cko = (tid & 3) * 8;
    const int lrow = lane & 15, lk = (lane >> 4) * 8;
    for (int it = 0; it < 6; it++) {
        CP_WAIT1();
        __syncthreads();
        if (it + 2 < 6) issue(it + 2, (it + 2) % 3);   // 3-stage: safe
        CP_COMMIT();
        const uint32_t bufb = sb + (it % 3) * G2_STAGE;
        {
            const int kc0 = it * 32;
            uint4 rw = *(const uint4*)(smem + (it % 3) * G2_STAGE + G2_A16 + crow * 80 + cko * 2);
            uint32_t parts[4] = { rw.x, rw.y, rw.z, rw.w };
            uint32_t hq[4];
            #pragma unroll
            for (int e = 0; e < 4; e++) {
                __half2 hp = *reinterpret_cast<__half2*>(&parts[e]);
                int c = kc0 + cko + e * 2;
                float x = fmaxf(fmaf(__low2float(hp),  s_a[c],   s_b[c]),   0.0f);
                float y = fmaxf(fmaf(__high2float(hp), s_a[c+1], s_b[c+1]), 0.0f);
                hq[e] = pack2(x, y);
            }
            *(uint4*)(smem + G2_CAH + crow * 80 + cko * 2) = make_uint4(hq[0], hq[1], hq[2], hq[3]);
        }
        __syncthreads();
        #pragma unroll
        for (int s = 0; s < 2; s++) {
            const int kc = s * 16;
            uint32_t fA[2][4];
            #pragma unroll
            for (int mf = 0; mf < 2; mf++) {
                uint32_t off = (uint32_t)(((wm * 32 + mf * 16 + lrow) * 40 + kc + lk) * 2);
                LDSM4(fA[mf][0], fA[mf][1], fA[mf][2], fA[mf][3], sb + G2_CAH + off);
            }
            uint32_t fB[4][2];
            #pragma unroll
            for (int q = 0; q < 2; q++) {
                uint32_t off = (uint32_t)(((wn * 32 + q * 16 + lrow) * 40 + kc + lk) * 2);
                uint32_t r0, r1, r2, r3;
                LDSM4(r0, r1, r2, r3, bufb + G2_B + off);
                fB[q*2][0] = r0; fB[q*2][1] = r2;
                fB[q*2+1][0] = r1; fB[q*2+1][1] = r3;
            }
            #pragma unroll
            for (int mf = 0; mf < 2; mf++)
                #pragma unroll
                for (int nf = 0; nf < 4; nf++)
                    MMA16816(acc[mf][nf], fA[mf][0], fA[mf][1], fA[mf][2], fA[mf][3],
                             fB[nf][0], fB[nf][1]);
        }
        __syncthreads();
    }

    const int g = lane >> 2, tig = lane & 3;
    float gs[16];
    #pragma unroll
    for (int i = 0; i < 16; i++) gs[i] = 0.0f;
    #pragma unroll
    for (int mf = 0; mf < 2; mf++)
        #pragma unroll
        for (int nf = 0; nf < 4; nf++) {
            int row = m0 + wm * 32 + mf * 16 + g;
            int col = wn * 32 + nf * 8 + tig * 2;
            float d0 = acc[mf][nf][0], d1 = acc[mf][nf][1];
            float d2 = acc[mf][nf][2], d3 = acc[mf][nf][3];
            *(float2*)(Out + (size_t)row * COUT + col)       = make_float2(d0, d1);
            *(float2*)(Out + (size_t)(row + 8) * COUT + col) = make_float2(d2, d3);
            int grp = col >> 4;
            gs[grp]     += d0 + d1 + d2 + d3;
            gs[8 + grp] += d0*d0 + d1*d1 + d2*d2 + d3*d3;
        }
    __syncthreads();
    float* red = (float*)smem;
    #pragma unroll
    for (int i = 0; i < 16; i++) red[i * 512 + tid] = gs[i];
    __syncthreads();
    for (int off = 256; off > 0; off >>= 1) {
        if (tid < off) {
            #pragma unroll
            for (int i = 0; i < 16; i++) red[i * 512 + tid] += red[i * 512 + tid + off];
        }
        __syncthreads();
    }
    if (tid < 16) {
        int cta = blockIdx.x & 127;
        int grp = tid & 7;
        part[(tid >= 8 ? 4096 : 0) + (bb * 8 + grp) * 128 + cta] = red[tid * 512];
    }
}

// ==================== GN final: parallel 128-thread reduce ====================
template<int CPG>
__global__ void __launch_bounds__(128) stats_final(
    const float* __restrict__ ps, const float* __restrict__ pss,
    const float* __restrict__ gamma, const float* __restrict__ beta,
    float* __restrict__ ac, float* __restrict__ bc, int Cdim)
{
    const int bg = blockIdx.x;
    const int b = bg >> 3, g = bg & 7;
    const int tid = threadIdx.x, lane = tid & 31, wrp = tid >> 5;
    __shared__ float sh[8];
    __shared__ float s_m, s_i;

    float s = ps[bg * 128 + tid], ss = pss[bg * 128 + tid];
    #pragma unroll
    for (int off = 16; off > 0; off >>= 1) {
        s  += __shfl_down_sync(0xFFFFFFFF, s,  off);
        ss += __shfl_down_sync(0xFFFFFFFF, ss, off);
    }
    if (lane == 0) { sh[wrp] = s; sh[4 + wrp] = ss; }
    __syncthreads();
    if (tid == 0) {
        float ts  = sh[0] + sh[1] + sh[2] + sh[3];
        float tss = sh[4] + sh[5] + sh[6] + sh[7];
        float cnt = (float)NPTS * (float)CPG;
        float mu  = ts / cnt;
        float var = tss / cnt - mu * mu;
        s_m = mu; s_i = rsqrtf(var + EPS_GN);
    }
    __syncthreads();
    if (tid < CPG) {
        int ch = g * CPG + tid;
        float a = gamma[ch] * s_i;
        ac[b * Cdim + ch] = a;
        bc[b * Cdim + ch] = beta[ch] - s_m * a;
    }
}

// ==================== finalize: vectorized float4 ====================
__global__ void __launch_bounds__(256) finalize_kernel(
    float* __restrict__ out, const float* __restrict__ a, const float* __restrict__ bc)
{
    size_t i4 = (size_t)blockIdx.x * 256 + threadIdx.x;
    int c0 = (int)(i4 & 31) * 4;
    int b  = (int)(i4 >> 19);
    const float* ap = a  + b * COUT + c0;
    const float* bp = bc + b * COUT + c0;
    float4 v = ((float4*)out)[i4];
    v.x = fmaxf(fmaf(v.x, ap[0], bp[0]), 0.0f);
    v.y = fmaxf(fmaf(v.y, ap[1], bp[1]), 0.0f);
    v.z = fmaxf(fmaf(v.z, ap[2], bp[2]), 0.0f);
    v.w = fmaxf(fmaf(v.w, ap[3], bp[3]), 0.0f);
    ((float4*)out)[i4] = v;
}

// ==================== launch ====================
extern "C" void kernel_launch(void* const* d_in, const int* in_sizes, int n_in,
                              void* d_out, int out_size)
{
    const float* fine_xyz    = (const float*)d_in[0];
    const float* coarse_xyz  = (const float*)d_in[1];
    const float* fine_feat   = (const float*)d_in[2];
    const float* coarse_feat = (const float*)d_in[3];
    const float* w1          = (const float*)d_in[4];
    const float* g1_w        = (const float*)d_in[5];
    const float* g1_b        = (const float*)d_in[6];
    const float* w2          = (const float*)d_in[7];
    const float* g2_w        = (const float*)d_in[8];
    const float* g2_b        = (const float*)d_in[9];
    float* out = (float*)d_out;

    __half *h1, *Pm, *w1h, *w2h;
    float *wt, *part1, *part2, *a1, *b1, *a2, *b2;
    int* idx;
    cudaGetSymbolAddress((void**)&h1, g_h1);
    cudaGetSymbolAddress((void**)&Pm, g_P);
    cudaGetSymbolAddress((void**)&idx, g_idx);
    cudaGetSymbolAddress((void**)&wt, g_wt);
    cudaGetSymbolAddress((void**)&w1h, g_w1h);
    cudaGetSymbolAddress((void**)&w2h, g_w2h);
    cudaGetSymbolAddress((void**)&part1, g_part1);
    cudaGetSymbolAddress((void**)&part2, g_part2);
    cudaGetSymbolAddress((void**)&a1, g_a1);
    cudaGetSymbolAddress((void**)&b1, g_b1);
    cudaGetSymbolAddress((void**)&a2, g_a2);
    cudaGetSymbolAddress((void**)&b2, g_b2);

    cudaFuncSetAttribute(pgemm_mma, cudaFuncAttributeMaxDynamicSharedMemorySize, P_SMEM);
    cudaFuncSetAttribute(gemm1_mma, cudaFuncAttributeMaxDynamicSharedMemorySize, F_SMEM);
    cudaFuncSetAttribute(gemm2_mma, cudaFuncAttributeMaxDynamicSharedMemorySize, G2_SMEM);

    knn_kernel<<<dim3(NPTS / 256, BATCH), 256>>>(fine_xyz, coarse_xyz, idx, wt);
    prep_weights<<<(CMID * CIN + COUT * CMID + 255) / 256, 256>>>(w1, w2, w1h, w2h);
    pgemm_mma<<<BATCH * (SPTS / 128), 512, P_SMEM>>>(coarse_feat, w1h, Pm);
    gemm1_mma<<<BN_TOTAL / 128, 512, F_SMEM>>>(fine_feat, Pm, idx, wt, w1h, h1, part1);
    stats_final<CMID / GROUPS><<<BATCH * GROUPS, 128>>>(part1, part1 + 4096, g1_w, g1_b, a1, b1, CMID);
    gemm2_mma<<<BN_TOTAL / 128, 512, G2_SMEM>>>(h1, w2h, a1, b1, out, part2);
    stats_final<COUT / GROUPS><<<BATCH * GROUPS, 128>>>(part2, part2 + 4096, g2_w, g2_b, a2, b2, COUT);
    finalize_kernel<<<(BN_TOTAL * COUT / 4) / 256, 256>>>(out, a2, b2);
}